// round 10
// baseline (speedup 1.0000x reference)
#include <cuda_runtime.h>

// ConvSBS fused contraction, warp-pair cooperative P=8, f32x2 SIMD.
// channels: [2, 8, 128, 128, 4] f32 ; cores: [4, 2, 8, 8, 4, 4] f32 ; out: [8,127,127,16] f32

typedef unsigned long long ull;

__device__ __forceinline__ ull pk2(float lo, float hi) {
    ull d; asm("mov.b64 %0, {%1, %2};" : "=l"(d) : "f"(lo), "f"(hi)); return d;
}
__device__ __forceinline__ float2 up2(ull v) {
    float2 r; asm("mov.b64 {%0, %1}, %2;" : "=f"(r.x), "=f"(r.y) : "l"(v)); return r;
}
__device__ __forceinline__ ull fma2(ull a, ull b, ull c) {
    ull d; asm("fma.rn.f32x2 %0, %1, %2, %3;" : "=l"(d) : "l"(a), "l"(b), "l"(c)); return d;
}
__device__ __forceinline__ ull mul2(ull a, ull b) {
    ull d; asm("mul.rn.f32x2 %0, %1, %2;" : "=l"(d) : "l"(a), "l"(b)); return d;
}
__device__ __forceinline__ ull add2(ull a, ull b) {
    ull d; asm("add.rn.f32x2 %0, %1, %2;" : "=l"(d) : "l"(a), "l"(b)); return d;
}

#define BATCH 8
#define H 128
#define W 128
#define OH 127
#define OW 127
#define GX 16                               // groups of 8 px per row
#define TOT_GROUPS (BATCH * OH * GX)        // 16256

#define WARPS_PER_CTA 8
#define NTHREADS (WARPS_PER_CTA * 32)
#define NCTAS 296
#define WPAIRS_PER_CTA 4

// Cores in smem, swizzled (4 KB per block bi): lane L owns lr (2L,2L+1);
// chunk c at ull idx bi*512 + L*16 + ((c+L)&7)*2.
//
// Per warp-PAIR: 4 pair buffers of 640 ull.
//   M block stride 78: element (bi,row,col) at bi*78 + row*10 + col.
//   Overlay (per pair, stage-2-local): Bsm[rs][k][i] at rs*82+k*10+i;
//   Psm at 336 + (q*8+i)*10 + q*8 + o8.
#define MBS 78
#define PAIR_ULL 640
#define WPAIR_ULL (4 * PAIR_ULL)
#define CORES_F 8192
#define SMEM_F  (CORES_F + WPAIRS_PER_CTA * WPAIR_ULL * 2)

__global__ void __launch_bounds__(NTHREADS, 2) convsbs_kernel(
    const float* __restrict__ channels,
    const float* __restrict__ cores,
    float* __restrict__ out)
{
    extern __shared__ float smem[];
    const int tid = threadIdx.x;
    ull* coreU = (ull*)smem;

    // cores relayout: [t][q][l][r][a][c4] -> swizzled per-lane chunks
    for (int idx = tid; idx < 8192; idx += NTHREADS) {
        int c4 = idx & 3, a = (idx >> 2) & 3, r = (idx >> 4) & 7;
        int l = (idx >> 7) & 7, q = (idx >> 10) & 1, t = idx >> 11;
        int bi = t * 2 + q;
        int lr = l * 8 + r;
        int L = lr >> 1, half = lr & 1;
        int ac = a * 4 + c4;
        int chunk = ac >> 1, pos = ac & 1;
        int uidx = bi * 512 + L * 16 + (((chunk + L) & 7) << 1) + pos;
        smem[uidx * 2 + half] = cores[idx];
    }
    __syncthreads();

    const int warp = tid >> 5;
    const int lane = tid & 31;
    const int wsub = warp & 1;          // 0: t=0,1 ; 1: t=2,3
    const int wp   = warp >> 1;         // warp-pair index in CTA
    const int barid = wp + 1;           // named barrier per warp-pair
    ull* PB = (ull*)(smem + CORES_F) + wp * WPAIR_ULL;

    const int g2 = lane >> 4;        // q (A-stage) / s (B-stage) / q (final)
    const int i2 = (lane >> 1) & 7;  // i (A) / k (B) / i (final)
    const int h2 = lane & 1;         // k-half (A) / i-half (B)

    const float* __restrict__ ch0 = channels;
    const float* __restrict__ ch1 = channels + BATCH * H * W * 4;
    const ull z = pk2(0.f, 0.f);
    const int nwork = gridDim.x * WPAIRS_PER_CTA;

    for (int g = blockIdx.x * WPAIRS_PER_CTA + wp; g < TOT_GROUPS; g += nwork) {
        int b   = g / (OH * GX);
        int rem = g - b * (OH * GX);
        int y   = rem >> 4;
        int x0  = (rem & 15) << 3;          // group covers out-x x0..x0+7

        // ========== Stage 1: this warp computes its 2 t-blocks for all 4 pairs ==========
        #pragma unroll
        for (int tt = 0; tt < 2; tt++) {
            const int t   = wsub * 2 + tt;
            const int py  = y + wsub;           // t>>1 == wsub
            const int cxb = x0 + tt;            // t&1 == tt
            const int rowbase = ((b * H + py) * W) * 4;

            // pack channels for 4 pixel-pairs
            ull c0p[4][4], c1p[4][4];
            #pragma unroll
            for (int p = 0; p < 4; p++) {
                const int xA = min(cxb + 2 * p, W - 1);
                const int xB = min(cxb + 2 * p + 1, W - 1);
                float4 u0 = *(const float4*)(ch0 + rowbase + 4 * xA);
                float4 u1 = *(const float4*)(ch0 + rowbase + 4 * xB);
                c0p[p][0] = pk2(u0.x, u1.x); c0p[p][1] = pk2(u0.y, u1.y);
                c0p[p][2] = pk2(u0.z, u1.z); c0p[p][3] = pk2(u0.w, u1.w);
                float4 w0 = *(const float4*)(ch1 + rowbase + 4 * xA);
                float4 w1 = *(const float4*)(ch1 + rowbase + 4 * xB);
                c1p[p][0] = pk2(w0.x, w1.x); c1p[p][1] = pk2(w0.y, w1.y);
                c1p[p][2] = pk2(w0.z, w1.z); c1p[p][3] = pk2(w0.w, w1.w);
            }

            const int midx0 = (lane >> 2) * 10 + 2 * (lane & 3);
            #pragma unroll
            for (int q = 0; q < 2; q++) {
                const int bi = t * 2 + q;
                const float4* cp4 = (const float4*)(coreU + bi * 512 + lane * 16);
                ull acc[4][2];
                #pragma unroll
                for (int p = 0; p < 4; p++) { acc[p][0] = z; acc[p][1] = z; }
                #pragma unroll
                for (int c = 0; c < 8; c++) {
                    const int a  = c >> 1;
                    const int cb = (2 * c) & 3;
                    float4 f = cp4[(c + lane) & 7];   // ac=2c: (f.x,f.y); ac=2c+1: (f.z,f.w)
                    ull cx2 = pk2(f.x, f.x);
                    ull cy2 = pk2(f.y, f.y);
                    ull cz2 = pk2(f.z, f.z);
                    ull cw2 = pk2(f.w, f.w);
                    #pragma unroll
                    for (int p = 0; p < 4; p++) {
                        ull vv0 = mul2(c0p[p][a], c1p[p][cb]);
                        ull vv1 = mul2(c0p[p][a], c1p[p][cb + 1]);
                        acc[p][0] = fma2(cx2, vv0, acc[p][0]);
                        acc[p][1] = fma2(cy2, vv0, acc[p][1]);
                        acc[p][0] = fma2(cz2, vv1, acc[p][0]);
                        acc[p][1] = fma2(cw2, vv1, acc[p][1]);
                    }
                }
                const int midx = bi * MBS + midx0;
                #pragma unroll
                for (int p = 0; p < 4; p++)
                    *(ulonglong2*)(PB + p * PAIR_ULL + midx) =
                        make_ulonglong2(acc[p][0], acc[p][1]);
            }
        }
        // exchange with partner warp
        asm volatile("bar.sync %0, 64;" :: "r"(barid) : "memory");

        // ========== Stage 2: this warp handles pairs wsub*2 + {0,1} ==========
        #pragma unroll
        for (int pp = 0; pp < 2; pp++) {
            const int pr = wsub * 2 + pp;
            ull* M = PB + pr * PAIR_ULL;

            // ---- A-stage: lane (q=g2, i=i2, kh=h2), both p accumulated ----
            ull a2[2][4];
            {
                ull rm0[2][8];
                #pragma unroll
                for (int p = 0; p < 2; p++) {
                    #pragma unroll
                    for (int c = 0; c < 4; c++) {
                        ulonglong2 u = *(const ulonglong2*)(M + p * MBS + i2 * 10 + 2 * c);
                        rm0[p][2 * c] = u.x; rm0[p][2 * c + 1] = u.y;
                    }
                }
                #pragma unroll
                for (int p = 0; p < 2; p++)
                    #pragma unroll
                    for (int kk = 0; kk < 4; kk++) a2[p][kk] = z;
                #pragma unroll
                for (int j = 0; j < 8; j++) {
                    ulonglong2 m1a = *(const ulonglong2*)(M + (2 + g2) * MBS + j * 10 + h2 * 4);
                    ulonglong2 m1b = *(const ulonglong2*)(M + (2 + g2) * MBS + j * 10 + h2 * 4 + 2);
                    #pragma unroll
                    for (int p = 0; p < 2; p++) {
                        a2[p][0] = fma2(rm0[p][j], m1a.x, a2[p][0]);
                        a2[p][1] = fma2(rm0[p][j], m1a.y, a2[p][1]);
                        a2[p][2] = fma2(rm0[p][j], m1b.x, a2[p][2]);
                        a2[p][3] = fma2(rm0[p][j], m1b.y, a2[p][3]);
                    }
                }
            }

            // ---- B-stage: lane (s=g2, k=i2, ih=h2), both r accumulated ----
            ull bt[2][4];
            {
                ull rm2[2][8];
                #pragma unroll
                for (int r = 0; r < 2; r++) {
                    #pragma unroll
                    for (int c = 0; c < 4; c++) {
                        ulonglong2 u = *(const ulonglong2*)(M + (4 + r) * MBS + i2 * 10 + 2 * c);
                        rm2[r][2 * c] = u.x; rm2[r][2 * c + 1] = u.y;
                    }
                }
                #pragma unroll
                for (int r = 0; r < 2; r++)
                    #pragma unroll
                    for (int ii = 0; ii < 4; ii++) bt[r][ii] = z;
                #pragma unroll
                for (int l = 0; l < 8; l++) {
                    ulonglong2 m3a = *(const ulonglong2*)(M + (6 + g2) * MBS + l * 10 + h2 * 4);
                    ulonglong2 m3b = *(const ulonglong2*)(M + (6 + g2) * MBS + l * 10 + h2 * 4 + 2);
                    #pragma unroll
                    for (int r = 0; r < 2; r++) {
                        bt[r][0] = fma2(rm2[r][l], m3a.x, bt[r][0]);
                        bt[r][1] = fma2(rm2[r][l], m3a.y, bt[r][1]);
                        bt[r][2] = fma2(rm2[r][l], m3b.x, bt[r][2]);
                        bt[r][3] = fma2(rm2[r][l], m3b.y, bt[r][3]);
                    }
                }
            }
            __syncwarp();

            // ---- store B: Bsm[rs][k][i] at rs*82 + k*10 + i  (rs = r*2 + s) ----
            #pragma unroll
            for (int r = 0; r < 2; r++) {
                const int base = (r * 2 + g2) * 82 + i2 * 10 + h2 * 4;
                *(ulonglong2*)(M + base)     = make_ulonglong2(bt[r][0], bt[r][1]);
                *(ulonglong2*)(M + base + 2) = make_ulonglong2(bt[r][2], bt[r][3]);
            }
            __syncwarp();

            // ---- final partials at lane (q=g2, i=i2, kh=h2) ----
            ull part[2][4];
            #pragma unroll
            for (int p = 0; p < 2; p++)
                #pragma unroll
                for (int rs = 0; rs < 4; rs++) part[p][rs] = z;
            #pragma unroll
            for (int rs = 0; rs < 4; rs++) {
                #pragma unroll
                for (int kk = 0; kk < 4; kk++) {
                    ull Bv = M[rs * 82 + (h2 * 4 + kk) * 10 + i2];
                    part[0][rs] = fma2(a2[0][kk], Bv, part[0][rs]);
                    part[1][rs] = fma2(a2[1][kk], Bv, part[1][rs]);
                }
            }
            #pragma unroll
            for (int p = 0; p < 2; p++)
                #pragma unroll
                for (int rs = 0; rs < 4; rs++)
                    part[p][rs] = add2(part[p][rs],
                                       __shfl_xor_sync(0xffffffffu, part[p][rs], 1));
            if (h2 == 0) {
                const int pbase = 336 + (g2 * 8 + i2) * 10 + g2 * 8;
                *(ulonglong2*)(M + pbase)     = make_ulonglong2(part[0][0], part[0][1]);
                *(ulonglong2*)(M + pbase + 2) = make_ulonglong2(part[0][2], part[0][3]);
                *(ulonglong2*)(M + pbase + 4) = make_ulonglong2(part[1][0], part[1][1]);
                *(ulonglong2*)(M + pbase + 6) = make_ulonglong2(part[1][2], part[1][3]);
            }
            __syncwarp();

            // ---- output: lanes 0..15, q=lane>>3, o8=lane&7 (p=o8>>2, rs=o8&3) ----
            if (lane < 16) {
                const int q = lane >> 3, o8 = lane & 7;
                ull s = z;
                #pragma unroll
                for (int i = 0; i < 8; i++)
                    s = add2(s, M[336 + (q * 8 + i) * 10 + q * 8 + o8]);
                const int p = o8 >> 2, rs = o8 & 3;
                const int outIdx = p * 8 + q * 4 + rs;
                const int xx = x0 + pr * 2;
                const int pix0 = (b * OH + y) * OW + xx;
                float2 pv = up2(s);
                out[pix0 * 16 + outIdx] = pv.x;
                if (xx + 1 < OW)
                    out[(pix0 + 1) * 16 + outIdx] = pv.y;
            }
            __syncwarp();
        }
        // all stage-2 reads of this group's buffers complete before next stage-1 writes
        asm volatile("bar.sync %0, 64;" :: "r"(barid) : "memory");
    }
}

extern "C" void kernel_launch(void* const* d_in, const int* in_sizes, int n_in,
                              void* d_out, int out_size)
{
    const float* channels = (const float*)d_in[0];
    const float* cores    = (const float*)d_in[1];
    float* out            = (float*)d_out;

    static bool attr_set = false;
    if (!attr_set) {
        cudaFuncSetAttribute(convsbs_kernel,
                             cudaFuncAttributeMaxDynamicSharedMemorySize,
                             SMEM_F * sizeof(float));
        attr_set = true;
    }
    convsbs_kernel<<<NCTAS, NTHREADS, SMEM_F * sizeof(float)>>>(channels, cores, out);
}

// round 11
// speedup vs baseline: 1.9117x; 1.9117x over previous
#include <cuda_runtime.h>

// ConvSBS fused contraction, warp-pair cooperative P=8, f32x2 SIMD,
// stage-1 split into two 2-pair passes to avoid register spills.
// channels: [2, 8, 128, 128, 4] f32 ; cores: [4, 2, 8, 8, 4, 4] f32 ; out: [8,127,127,16] f32

typedef unsigned long long ull;

__device__ __forceinline__ ull pk2(float lo, float hi) {
    ull d; asm("mov.b64 %0, {%1, %2};" : "=l"(d) : "f"(lo), "f"(hi)); return d;
}
__device__ __forceinline__ float2 up2(ull v) {
    float2 r; asm("mov.b64 {%0, %1}, %2;" : "=f"(r.x), "=f"(r.y) : "l"(v)); return r;
}
__device__ __forceinline__ ull fma2(ull a, ull b, ull c) {
    ull d; asm("fma.rn.f32x2 %0, %1, %2, %3;" : "=l"(d) : "l"(a), "l"(b), "l"(c)); return d;
}
__device__ __forceinline__ ull mul2(ull a, ull b) {
    ull d; asm("mul.rn.f32x2 %0, %1, %2;" : "=l"(d) : "l"(a), "l"(b)); return d;
}
__device__ __forceinline__ ull add2(ull a, ull b) {
    ull d; asm("add.rn.f32x2 %0, %1, %2;" : "=l"(d) : "l"(a), "l"(b)); return d;
}

#define BATCH 8
#define H 128
#define W 128
#define OH 127
#define OW 127
#define GX 16                               // groups of 8 px per row
#define TOT_GROUPS (BATCH * OH * GX)        // 16256

#define WARPS_PER_CTA 8
#define NTHREADS (WARPS_PER_CTA * 32)
#define NCTAS 296
#define WPAIRS_PER_CTA 4

// Cores in smem, swizzled (4 KB per block bi): lane L owns lr (2L,2L+1);
// chunk c at ull idx bi*512 + L*16 + ((c+L)&7)*2.
//
// Per warp-PAIR: 4 pair buffers of 640 ull.
//   M block stride 78: element (bi,row,col) at bi*78 + row*10 + col.
//   Overlay (per pair, stage-2-local): Bsm[rs][k][i] at rs*82+k*10+i;
//   Psm at 336 + (q*8+i)*10 + q*8 + o8.
#define MBS 78
#define PAIR_ULL 640
#define WPAIR_ULL (4 * PAIR_ULL)
#define CORES_F 8192
#define SMEM_F  (CORES_F + WPAIRS_PER_CTA * WPAIR_ULL * 2)

__global__ void __launch_bounds__(NTHREADS, 2) convsbs_kernel(
    const float* __restrict__ channels,
    const float* __restrict__ cores,
    float* __restrict__ out)
{
    extern __shared__ float smem[];
    const int tid = threadIdx.x;
    ull* coreU = (ull*)smem;

    // cores relayout: [t][q][l][r][a][c4] -> swizzled per-lane chunks
    for (int idx = tid; idx < 8192; idx += NTHREADS) {
        int c4 = idx & 3, a = (idx >> 2) & 3, r = (idx >> 4) & 7;
        int l = (idx >> 7) & 7, q = (idx >> 10) & 1, t = idx >> 11;
        int bi = t * 2 + q;
        int lr = l * 8 + r;
        int L = lr >> 1, half = lr & 1;
        int ac = a * 4 + c4;
        int chunk = ac >> 1, pos = ac & 1;
        int uidx = bi * 512 + L * 16 + (((chunk + L) & 7) << 1) + pos;
        smem[uidx * 2 + half] = cores[idx];
    }
    __syncthreads();

    const int warp = tid >> 5;
    const int lane = tid & 31;
    const int wsub = warp & 1;          // 0: t=0,1 ; 1: t=2,3
    const int wp   = warp >> 1;         // warp-pair index in CTA
    const int barid = wp + 1;           // named barrier per warp-pair
    ull* PB = (ull*)(smem + CORES_F) + wp * WPAIR_ULL;

    const int g2 = lane >> 4;        // q (A-stage) / s (B-stage) / q (final)
    const int i2 = (lane >> 1) & 7;  // i (A) / k (B) / i (final)
    const int h2 = lane & 1;         // k-half (A) / i-half (B)

    const float* __restrict__ ch0 = channels;
    const float* __restrict__ ch1 = channels + BATCH * H * W * 4;
    const ull z = pk2(0.f, 0.f);
    const int nwork = gridDim.x * WPAIRS_PER_CTA;

    for (int g = blockIdx.x * WPAIRS_PER_CTA + wp; g < TOT_GROUPS; g += nwork) {
        int b   = g / (OH * GX);
        int rem = g - b * (OH * GX);
        int y   = rem >> 4;
        int x0  = (rem & 15) << 3;          // group covers out-x x0..x0+7

        // ========== Stage 1: this warp computes t = wsub*2 + {0,1} for all 4 pairs,
        //                     two passes of 2 pairs to bound register pressure ==========
        const int py      = y + wsub;
        const int rowbase = ((b * H + py) * W) * 4;
        const int midx0   = (lane >> 2) * 10 + 2 * (lane & 3);

        #pragma unroll 1
        for (int p2 = 0; p2 < 2; p2++) {
            #pragma unroll
            for (int tt = 0; tt < 2; tt++) {
                const int t   = wsub * 2 + tt;
                const int cxb = x0 + tt;

                // pack channels for pairs p2*2, p2*2+1
                ull c0p[2][4], c1p[2][4];
                #pragma unroll
                for (int pp = 0; pp < 2; pp++) {
                    const int p  = p2 * 2 + pp;
                    const int xA = min(cxb + 2 * p, W - 1);
                    const int xB = min(cxb + 2 * p + 1, W - 1);
                    float4 u0 = *(const float4*)(ch0 + rowbase + 4 * xA);
                    float4 u1 = *(const float4*)(ch0 + rowbase + 4 * xB);
                    c0p[pp][0] = pk2(u0.x, u1.x); c0p[pp][1] = pk2(u0.y, u1.y);
                    c0p[pp][2] = pk2(u0.z, u1.z); c0p[pp][3] = pk2(u0.w, u1.w);
                    float4 w0 = *(const float4*)(ch1 + rowbase + 4 * xA);
                    float4 w1 = *(const float4*)(ch1 + rowbase + 4 * xB);
                    c1p[pp][0] = pk2(w0.x, w1.x); c1p[pp][1] = pk2(w0.y, w1.y);
                    c1p[pp][2] = pk2(w0.z, w1.z); c1p[pp][3] = pk2(w0.w, w1.w);
                }

                #pragma unroll
                for (int q = 0; q < 2; q++) {
                    const int bi = t * 2 + q;
                    const float4* cp4 = (const float4*)(coreU + bi * 512 + lane * 16);
                    ull acc[2][2];
                    acc[0][0] = z; acc[0][1] = z; acc[1][0] = z; acc[1][1] = z;
                    #pragma unroll
                    for (int c = 0; c < 8; c++) {
                        const int a  = c >> 1;
                        const int cb = (2 * c) & 3;
                        float4 f = cp4[(c + lane) & 7];   // ac=2c: (f.x,f.y); 2c+1: (f.z,f.w)
                        ull cx2 = pk2(f.x, f.x);
                        ull cy2 = pk2(f.y, f.y);
                        ull cz2 = pk2(f.z, f.z);
                        ull cw2 = pk2(f.w, f.w);
                        #pragma unroll
                        for (int pp = 0; pp < 2; pp++) {
                            ull vv0 = mul2(c0p[pp][a], c1p[pp][cb]);
                            ull vv1 = mul2(c0p[pp][a], c1p[pp][cb + 1]);
                            acc[pp][0] = fma2(cx2, vv0, acc[pp][0]);
                            acc[pp][1] = fma2(cy2, vv0, acc[pp][1]);
                            acc[pp][0] = fma2(cz2, vv1, acc[pp][0]);
                            acc[pp][1] = fma2(cw2, vv1, acc[pp][1]);
                        }
                    }
                    const int midx = bi * MBS + midx0;
                    #pragma unroll
                    for (int pp = 0; pp < 2; pp++)
                        *(ulonglong2*)(PB + (p2 * 2 + pp) * PAIR_ULL + midx) =
                            make_ulonglong2(acc[pp][0], acc[pp][1]);
                }
            }
        }
        // exchange with partner warp
        asm volatile("bar.sync %0, 64;" :: "r"(barid) : "memory");

        // ========== Stage 2: this warp handles pairs wsub*2 + {0,1} ==========
        #pragma unroll
        for (int pp = 0; pp < 2; pp++) {
            const int pr = wsub * 2 + pp;
            ull* M = PB + pr * PAIR_ULL;

            // ---- A-stage: lane (q=g2, i=i2, kh=h2), both p accumulated ----
            ull a2[2][4];
            {
                ull rm0[2][8];
                #pragma unroll
                for (int p = 0; p < 2; p++) {
                    #pragma unroll
                    for (int c = 0; c < 4; c++) {
                        ulonglong2 u = *(const ulonglong2*)(M + p * MBS + i2 * 10 + 2 * c);
                        rm0[p][2 * c] = u.x; rm0[p][2 * c + 1] = u.y;
                    }
                }
                #pragma unroll
                for (int p = 0; p < 2; p++)
                    #pragma unroll
                    for (int kk = 0; kk < 4; kk++) a2[p][kk] = z;
                #pragma unroll
                for (int j = 0; j < 8; j++) {
                    ulonglong2 m1a = *(const ulonglong2*)(M + (2 + g2) * MBS + j * 10 + h2 * 4);
                    ulonglong2 m1b = *(const ulonglong2*)(M + (2 + g2) * MBS + j * 10 + h2 * 4 + 2);
                    #pragma unroll
                    for (int p = 0; p < 2; p++) {
                        a2[p][0] = fma2(rm0[p][j], m1a.x, a2[p][0]);
                        a2[p][1] = fma2(rm0[p][j], m1a.y, a2[p][1]);
                        a2[p][2] = fma2(rm0[p][j], m1b.x, a2[p][2]);
                        a2[p][3] = fma2(rm0[p][j], m1b.y, a2[p][3]);
                    }
                }
            }

            // ---- B-stage: lane (s=g2, k=i2, ih=h2), both r accumulated ----
            ull bt[2][4];
            {
                ull rm2[2][8];
                #pragma unroll
                for (int r = 0; r < 2; r++) {
                    #pragma unroll
                    for (int c = 0; c < 4; c++) {
                        ulonglong2 u = *(const ulonglong2*)(M + (4 + r) * MBS + i2 * 10 + 2 * c);
                        rm2[r][2 * c] = u.x; rm2[r][2 * c + 1] = u.y;
                    }
                }
                #pragma unroll
                for (int r = 0; r < 2; r++)
                    #pragma unroll
                    for (int ii = 0; ii < 4; ii++) bt[r][ii] = z;
                #pragma unroll
                for (int l = 0; l < 8; l++) {
                    ulonglong2 m3a = *(const ulonglong2*)(M + (6 + g2) * MBS + l * 10 + h2 * 4);
                    ulonglong2 m3b = *(const ulonglong2*)(M + (6 + g2) * MBS + l * 10 + h2 * 4 + 2);
                    #pragma unroll
                    for (int r = 0; r < 2; r++) {
                        bt[r][0] = fma2(rm2[r][l], m3a.x, bt[r][0]);
                        bt[r][1] = fma2(rm2[r][l], m3a.y, bt[r][1]);
                        bt[r][2] = fma2(rm2[r][l], m3b.x, bt[r][2]);
                        bt[r][3] = fma2(rm2[r][l], m3b.y, bt[r][3]);
                    }
                }
            }
            __syncwarp();

            // ---- store B: Bsm[rs][k][i] at rs*82 + k*10 + i  (rs = r*2 + s) ----
            #pragma unroll
            for (int r = 0; r < 2; r++) {
                const int base = (r * 2 + g2) * 82 + i2 * 10 + h2 * 4;
                *(ulonglong2*)(M + base)     = make_ulonglong2(bt[r][0], bt[r][1]);
                *(ulonglong2*)(M + base + 2) = make_ulonglong2(bt[r][2], bt[r][3]);
            }
            __syncwarp();

            // ---- final partials at lane (q=g2, i=i2, kh=h2) ----
            ull part[2][4];
            #pragma unroll
            for (int p = 0; p < 2; p++)
                #pragma unroll
                for (int rs = 0; rs < 4; rs++) part[p][rs] = z;
            #pragma unroll
            for (int rs = 0; rs < 4; rs++) {
                #pragma unroll
                for (int kk = 0; kk < 4; kk++) {
                    ull Bv = M[rs * 82 + (h2 * 4 + kk) * 10 + i2];
                    part[0][rs] = fma2(a2[0][kk], Bv, part[0][rs]);
                    part[1][rs] = fma2(a2[1][kk], Bv, part[1][rs]);
                }
            }
            #pragma unroll
            for (int p = 0; p < 2; p++)
                #pragma unroll
                for (int rs = 0; rs < 4; rs++)
                    part[p][rs] = add2(part[p][rs],
                                       __shfl_xor_sync(0xffffffffu, part[p][rs], 1));
            if (h2 == 0) {
                const int pbase = 336 + (g2 * 8 + i2) * 10 + g2 * 8;
                *(ulonglong2*)(M + pbase)     = make_ulonglong2(part[0][0], part[0][1]);
                *(ulonglong2*)(M + pbase + 2) = make_ulonglong2(part[0][2], part[0][3]);
                *(ulonglong2*)(M + pbase + 4) = make_ulonglong2(part[1][0], part[1][1]);
                *(ulonglong2*)(M + pbase + 6) = make_ulonglong2(part[1][2], part[1][3]);
            }
            __syncwarp();

            // ---- output: lanes 0..15, q=lane>>3, o8=lane&7 (p=o8>>2, rs=o8&3) ----
            if (lane < 16) {
                const int q = lane >> 3, o8 = lane & 7;
                ull s = z;
                #pragma unroll
                for (int i = 0; i < 8; i++)
                    s = add2(s, M[336 + (q * 8 + i) * 10 + q * 8 + o8]);
                const int p = o8 >> 2, rs = o8 & 3;
                const int outIdx = p * 8 + q * 4 + rs;
                const int xx = x0 + pr * 2;
                const int pix0 = (b * OH + y) * OW + xx;
                float2 pv = up2(s);
                out[pix0 * 16 + outIdx] = pv.x;
                if (xx + 1 < OW)
                    out[(pix0 + 1) * 16 + outIdx] = pv.y;
            }
            __syncwarp();
        }
        // all stage-2 reads of this group's buffers complete before next stage-1 writes
        asm volatile("bar.sync %0, 64;" :: "r"(barid) : "memory");
    }
}

extern "C" void kernel_launch(void* const* d_in, const int* in_sizes, int n_in,
                              void* d_out, int out_size)
{
    const float* channels = (const float*)d_in[0];
    const float* cores    = (const float*)d_in[1];
    float* out            = (float*)d_out;

    static bool attr_set = false;
    if (!attr_set) {
        cudaFuncSetAttribute(convsbs_kernel,
                             cudaFuncAttributeMaxDynamicSharedMemorySize,
                             SMEM_F * sizeof(float));
        attr_set = true;
    }
    convsbs_kernel<<<NCTAS, NTHREADS, SMEM_F * sizeof(float)>>>(channels, cores, out);
}

// round 12
// speedup vs baseline: 2.2501x; 1.1770x over previous
#include <cuda_runtime.h>

// ConvSBS fused contraction, warp-pair cooperative P=8, f32x2 SIMD.
// Channels pre-transposed into packed pixel-pair tables so stage-1 loads them
// directly as aligned 8-byte words (no float4->ull repacking, no reg blowup).
// channels: [2, 8, 128, 128, 4] f32 ; cores: [4, 2, 8, 8, 4, 4] f32 ; out: [8,127,127,16] f32

typedef unsigned long long ull;

__device__ __forceinline__ ull pk2(float lo, float hi) {
    ull d; asm("mov.b64 %0, {%1, %2};" : "=l"(d) : "f"(lo), "f"(hi)); return d;
}
__device__ __forceinline__ float2 up2(ull v) {
    float2 r; asm("mov.b64 {%0, %1}, %2;" : "=f"(r.x), "=f"(r.y) : "l"(v)); return r;
}
__device__ __forceinline__ ull fma2(ull a, ull b, ull c) {
    ull d; asm("fma.rn.f32x2 %0, %1, %2, %3;" : "=l"(d) : "l"(a), "l"(b), "l"(c)); return d;
}
__device__ __forceinline__ ull mul2(ull a, ull b) {
    ull d; asm("mul.rn.f32x2 %0, %1, %2;" : "=l"(d) : "l"(a), "l"(b)); return d;
}
__device__ __forceinline__ ull add2(ull a, ull b) {
    ull d; asm("add.rn.f32x2 %0, %1, %2;" : "=l"(d) : "l"(a), "l"(b)); return d;
}

#define BATCH 8
#define H 128
#define W 128
#define OH 127
#define OW 127
#define GX 16                               // groups of 8 px per row
#define TOT_GROUPS (BATCH * OH * GX)        // 16256

#define WARPS_PER_CTA 8
#define NTHREADS (WARPS_PER_CTA * 32)
#define NCTAS 296
#define WPAIRS_PER_CTA 4

// Packed pixel-pair channel tables: [ch][b][y][a][j]
//   chE[..][j] = (px 2j,   px 2j+1)
//   chO[..][j] = (px 2j+1, px min(2j+2,127))
__device__ ull g_chE[2][BATCH][H][4][64];
__device__ ull g_chO[2][BATCH][H][4][64];

#define MBS 78
#define PAIR_ULL 640
#define WPAIR_ULL (4 * PAIR_ULL)
#define CORES_F 8192
#define SMEM_F  (CORES_F + WPAIRS_PER_CTA * WPAIR_ULL * 2)

__global__ void transpose_kernel(const float* __restrict__ channels) {
    int idx = blockIdx.x * blockDim.x + threadIdx.x;   // 2*8*128*4*64 = 524288
    if (idx >= 2 * BATCH * H * 4 * 64) return;
    int j = idx & 63, a = (idx >> 6) & 3, y = (idx >> 8) & 127;
    int b = (idx >> 15) & 7, c = idx >> 18;
    const float* base = channels + (((c * BATCH + b) * H + y) * W) * 4;
    float e0 = base[(2 * j) * 4 + a];
    float e1 = base[(2 * j + 1) * 4 + a];
    int x2 = min(2 * j + 2, W - 1);
    float o1 = base[x2 * 4 + a];
    g_chE[c][b][y][a][j] = pk2(e0, e1);
    g_chO[c][b][y][a][j] = pk2(e1, o1);
}

__global__ void __launch_bounds__(NTHREADS, 2) convsbs_kernel(
    const float* __restrict__ cores,
    float* __restrict__ out)
{
    extern __shared__ float smem[];
    const int tid = threadIdx.x;
    ull* coreU = (ull*)smem;

    // cores relayout: [t][q][l][r][a][c4] -> swizzled per-lane chunks
    // lane L owns lr (2L,2L+1); chunk c at ull idx bi*512 + L*16 + ((c+L)&7)*2.
    for (int idx = tid; idx < 8192; idx += NTHREADS) {
        int c4 = idx & 3, a = (idx >> 2) & 3, r = (idx >> 4) & 7;
        int l = (idx >> 7) & 7, q = (idx >> 10) & 1, t = idx >> 11;
        int bi = t * 2 + q;
        int lr = l * 8 + r;
        int L = lr >> 1, half = lr & 1;
        int ac = a * 4 + c4;
        int chunk = ac >> 1, pos = ac & 1;
        int uidx = bi * 512 + L * 16 + (((chunk + L) & 7) << 1) + pos;
        smem[uidx * 2 + half] = cores[idx];
    }
    __syncthreads();

    const int warp = tid >> 5;
    const int lane = tid & 31;
    const int wsub = warp & 1;          // 0: t=0,1 ; 1: t=2,3
    const int wp   = warp >> 1;         // warp-pair index in CTA
    const int barid = wp + 1;           // named barrier per warp-pair
    ull* PB = (ull*)(smem + CORES_F) + wp * WPAIR_ULL;

    const int g2 = lane >> 4;        // q (A-stage) / s (B-stage) / q (final)
    const int i2 = (lane >> 1) & 7;  // i (A) / k (B) / i (final)
    const int h2 = lane & 1;         // k-half (A) / i-half (B)

    const ull z = pk2(0.f, 0.f);
    const int nwork = gridDim.x * WPAIRS_PER_CTA;

    for (int g = blockIdx.x * WPAIRS_PER_CTA + wp; g < TOT_GROUPS; g += nwork) {
        int b   = g / (OH * GX);
        int rem = g - b * (OH * GX);
        int y   = rem >> 4;
        int x0  = (rem & 15) << 3;          // group covers out-x x0..x0+7

        // ========== Stage 1: this warp computes t = wsub*2 + {0,1} for all 4 pairs ==========
        const int py    = y + wsub;
        const int jbase = x0 >> 1;
        const int midx0 = (lane >> 2) * 10 + 2 * (lane & 3);

        #pragma unroll 1
        for (int tt = 0; tt < 2; tt++) {
            const int t = wsub * 2 + tt;
            const ull* T0 = tt ? &g_chO[0][b][py][0][jbase] : &g_chE[0][b][py][0][jbase];
            const ull* T1 = tt ? &g_chO[1][b][py][0][jbase] : &g_chE[1][b][py][0][jbase];

            // packed channels, loaded directly as ull (uniform-address broadcast LDG)
            ull c0[4][4], c1[4][4];    // [pair][a]
            #pragma unroll
            for (int p = 0; p < 4; p++)
                #pragma unroll
                for (int a = 0; a < 4; a++) {
                    c0[p][a] = T0[a * 64 + p];
                    c1[p][a] = T1[a * 64 + p];
                }

            #pragma unroll
            for (int q = 0; q < 2; q++) {
                const int bi = t * 2 + q;
                const float4* cp4 = (const float4*)(coreU + bi * 512 + lane * 16);
                ull acc[4][2];
                #pragma unroll
                for (int p = 0; p < 4; p++) { acc[p][0] = z; acc[p][1] = z; }
                #pragma unroll
                for (int c = 0; c < 8; c++) {
                    const int a  = c >> 1;          // ac = 2c -> a = c>>1, cb = (2c)&3
                    const int cb = (2 * c) & 3;
                    float4 f = cp4[(c + lane) & 7]; // ac=2c: (f.x,f.y); ac=2c+1: (f.z,f.w)
                    ull cx2 = pk2(f.x, f.x);
                    ull cy2 = pk2(f.y, f.y);
                    ull cz2 = pk2(f.z, f.z);
                    ull cw2 = pk2(f.w, f.w);
                    #pragma unroll
                    for (int p = 0; p < 4; p++) {
                        ull vv0 = mul2(c0[p][a], c1[p][cb]);
                        ull vv1 = mul2(c0[p][a], c1[p][cb + 1]);
                        acc[p][0] = fma2(cx2, vv0, acc[p][0]);
                        acc[p][1] = fma2(cy2, vv0, acc[p][1]);
                        acc[p][0] = fma2(cz2, vv1, acc[p][0]);
                        acc[p][1] = fma2(cw2, vv1, acc[p][1]);
                    }
                }
                const int midx = bi * MBS + midx0;
                #pragma unroll
                for (int p = 0; p < 4; p++)
                    *(ulonglong2*)(PB + p * PAIR_ULL + midx) =
                        make_ulonglong2(acc[p][0], acc[p][1]);
            }
        }
        // exchange with partner warp
        asm volatile("bar.sync %0, 64;" :: "r"(barid) : "memory");

        // ========== Stage 2: this warp handles pairs wsub*2 + {0,1} ==========
        #pragma unroll
        for (int pp = 0; pp < 2; pp++) {
            const int pr = wsub * 2 + pp;
            ull* M = PB + pr * PAIR_ULL;

            // ---- A-stage: lane (q=g2, i=i2, kh=h2), both p accumulated ----
            ull a2[2][4];
            {
                ull rm0[2][8];
                #pragma unroll
                for (int p = 0; p < 2; p++) {
                    #pragma unroll
                    for (int c = 0; c < 4; c++) {
                        ulonglong2 u = *(const ulonglong2*)(M + p * MBS + i2 * 10 + 2 * c);
                        rm0[p][2 * c] = u.x; rm0[p][2 * c + 1] = u.y;
                    }
                }
                #pragma unroll
                for (int p = 0; p < 2; p++)
                    #pragma unroll
                    for (int kk = 0; kk < 4; kk++) a2[p][kk] = z;
                #pragma unroll
                for (int j = 0; j < 8; j++) {
                    ulonglong2 m1a = *(const ulonglong2*)(M + (2 + g2) * MBS + j * 10 + h2 * 4);
                    ulonglong2 m1b = *(const ulonglong2*)(M + (2 + g2) * MBS + j * 10 + h2 * 4 + 2);
                    #pragma unroll
                    for (int p = 0; p < 2; p++) {
                        a2[p][0] = fma2(rm0[p][j], m1a.x, a2[p][0]);
                        a2[p][1] = fma2(rm0[p][j], m1a.y, a2[p][1]);
                        a2[p][2] = fma2(rm0[p][j], m1b.x, a2[p][2]);
                        a2[p][3] = fma2(rm0[p][j], m1b.y, a2[p][3]);
                    }
                }
            }

            // ---- B-stage: lane (s=g2, k=i2, ih=h2), both r accumulated ----
            ull bt[2][4];
            {
                ull rm2[2][8];
                #pragma unroll
                for (int r = 0; r < 2; r++) {
                    #pragma unroll
                    for (int c = 0; c < 4; c++) {
                        ulonglong2 u = *(const ulonglong2*)(M + (4 + r) * MBS + i2 * 10 + 2 * c);
                        rm2[r][2 * c] = u.x; rm2[r][2 * c + 1] = u.y;
                    }
                }
                #pragma unroll
                for (int r = 0; r < 2; r++)
                    #pragma unroll
                    for (int ii = 0; ii < 4; ii++) bt[r][ii] = z;
                #pragma unroll
                for (int l = 0; l < 8; l++) {
                    ulonglong2 m3a = *(const ulonglong2*)(M + (6 + g2) * MBS + l * 10 + h2 * 4);
                    ulonglong2 m3b = *(const ulonglong2*)(M + (6 + g2) * MBS + l * 10 + h2 * 4 + 2);
                    #pragma unroll
                    for (int r = 0; r < 2; r++) {
                        bt[r][0] = fma2(rm2[r][l], m3a.x, bt[r][0]);
                        bt[r][1] = fma2(rm2[r][l], m3a.y, bt[r][1]);
                        bt[r][2] = fma2(rm2[r][l], m3b.x, bt[r][2]);
                        bt[r][3] = fma2(rm2[r][l], m3b.y, bt[r][3]);
                    }
                }
            }
            __syncwarp();

            // ---- store B: Bsm[rs][k][i] at rs*82 + k*10 + i  (rs = r*2 + s) ----
            #pragma unroll
            for (int r = 0; r < 2; r++) {
                const int base = (r * 2 + g2) * 82 + i2 * 10 + h2 * 4;
                *(ulonglong2*)(M + base)     = make_ulonglong2(bt[r][0], bt[r][1]);
                *(ulonglong2*)(M + base + 2) = make_ulonglong2(bt[r][2], bt[r][3]);
            }
            __syncwarp();

            // ---- final partials at lane (q=g2, i=i2, kh=h2) ----
            ull part[2][4];
            #pragma unroll
            for (int p = 0; p < 2; p++)
                #pragma unroll
                for (int rs = 0; rs < 4; rs++) part[p][rs] = z;
            #pragma unroll
            for (int rs = 0; rs < 4; rs++) {
                #pragma unroll
                for (int kk = 0; kk < 4; kk++) {
                    ull Bv = M[rs * 82 + (h2 * 4 + kk) * 10 + i2];
                    part[0][rs] = fma2(a2[0][kk], Bv, part[0][rs]);
                    part[1][rs] = fma2(a2[1][kk], Bv, part[1][rs]);
                }
            }
            #pragma unroll
            for (int p = 0; p < 2; p++)
                #pragma unroll
                for (int rs = 0; rs < 4; rs++)
                    part[p][rs] = add2(part[p][rs],
                                       __shfl_xor_sync(0xffffffffu, part[p][rs], 1));
            if (h2 == 0) {
                const int pbase = 336 + (g2 * 8 + i2) * 10 + g2 * 8;
                *(ulonglong2*)(M + pbase)     = make_ulonglong2(part[0][0], part[0][1]);
                *(ulonglong2*)(M + pbase + 2) = make_ulonglong2(part[0][2], part[0][3]);
                *(ulonglong2*)(M + pbase + 4) = make_ulonglong2(part[1][0], part[1][1]);
                *(ulonglong2*)(M + pbase + 6) = make_ulonglong2(part[1][2], part[1][3]);
            }
            __syncwarp();

            // ---- output: lanes 0..15, q=lane>>3, o8=lane&7 (p=o8>>2, rs=o8&3) ----
            if (lane < 16) {
                const int q = lane >> 3, o8 = lane & 7;
                ull s = z;
                #pragma unroll
                for (int i = 0; i < 8; i++)
                    s = add2(s, M[336 + (q * 8 + i) * 10 + q * 8 + o8]);
                const int p = o8 >> 2, rs = o8 & 3;
                const int outIdx = p * 8 + q * 4 + rs;
                const int xx = x0 + pr * 2;
                const int pix0 = (b * OH + y) * OW + xx;
                float2 pv = up2(s);
                out[pix0 * 16 + outIdx] = pv.x;
                if (xx + 1 < OW)
                    out[(pix0 + 1) * 16 + outIdx] = pv.y;
            }
            __syncwarp();
        }
        // all stage-2 reads of this group's buffers complete before next stage-1 writes
        asm volatile("bar.sync %0, 64;" :: "r"(barid) : "memory");
    }
}

extern "C" void kernel_launch(void* const* d_in, const int* in_sizes, int n_in,
                              void* d_out, int out_size)
{
    const float* channels = (const float*)d_in[0];
    const float* cores    = (const float*)d_in[1];
    float* out            = (float*)d_out;

    static bool attr_set = false;
    if (!attr_set) {
        cudaFuncSetAttribute(convsbs_kernel,
                             cudaFuncAttributeMaxDynamicSharedMemorySize,
                             SMEM_F * sizeof(float));
        attr_set = true;
    }
    transpose_kernel<<<512, 1024>>>(channels);
    convsbs_kernel<<<NCTAS, NTHREADS, SMEM_F * sizeof(float)>>>(cores, out);
}

// round 14
// speedup vs baseline: 2.9653x; 1.3179x over previous
#include <cuda_runtime.h>

// ConvSBS fused contraction, pixel-pair SIMD (f32x2), R6 structure +
// pre-transposed packed pixel-pair channel tables (direct LDG.64 loads).
// channels: [2, 8, 128, 128, 4] f32 ; cores: [4, 2, 8, 8, 4, 4] f32 ; out: [8,127,127,16] f32

typedef unsigned long long ull;

__device__ __forceinline__ ull pk2(float lo, float hi) {
    ull d; asm("mov.b64 %0, {%1, %2};" : "=l"(d) : "f"(lo), "f"(hi)); return d;
}
__device__ __forceinline__ float2 up2(ull v) {
    float2 r; asm("mov.b64 {%0, %1}, %2;" : "=f"(r.x), "=f"(r.y) : "l"(v)); return r;
}
__device__ __forceinline__ ull fma2(ull a, ull b, ull c) {
    ull d; asm("fma.rn.f32x2 %0, %1, %2, %3;" : "=l"(d) : "l"(a), "l"(b), "l"(c)); return d;
}
__device__ __forceinline__ ull mul2(ull a, ull b) {
    ull d; asm("mul.rn.f32x2 %0, %1, %2;" : "=l"(d) : "l"(a), "l"(b)); return d;
}
__device__ __forceinline__ ull add2(ull a, ull b) {
    ull d; asm("add.rn.f32x2 %0, %1, %2;" : "=l"(d) : "l"(a), "l"(b)); return d;
}

#define BATCH 8
#define H 128
#define W 128
#define OH 127
#define OW 127
#define GX 32
#define TOT_GROUPS (BATCH * OH * GX)

#define WARPS_PER_CTA 8
#define NTHREADS (WARPS_PER_CTA * 32)
#define NCTAS 296

// Packed pixel-pair channel tables: [ch][b][y][a][j]
//   chE[..][j] = (px 2j,   px 2j+1)
//   chO[..][j] = (px 2j+1, px min(2j+2,127))
__device__ ull g_chE[2][BATCH][H][4][64];
__device__ ull g_chO[2][BATCH][H][4][64];

// Cores in smem, swizzled (4 KB per block bi): lane L owns lr (2L,2L+1);
// chunk c at ull idx bi*512 + L*16 + ((c+L)&7)*2.
//
// Per-pair scratch: 640 ull.
//   M element (bi,row,col) at ull idx bi*80 + row*10 + col.
//   Overlay: Bsm[rs][k][i] at rs*82 + k*10 + i ; Psm at 336 + (q*8+i)*10 + q*8 + o8.
#define MBS 80
#define PAIR_ULL 640
#define WARP_ULL (2 * PAIR_ULL)
#define CORES_F 8192
#define SMEM_F  (CORES_F + WARPS_PER_CTA * WARP_ULL * 2)

__global__ void transpose_kernel(const float* __restrict__ channels) {
    int idx = blockIdx.x * blockDim.x + threadIdx.x;   // 2*8*128*4*64 = 524288
    if (idx >= 2 * BATCH * H * 4 * 64) return;
    int j = idx & 63, a = (idx >> 6) & 3, y = (idx >> 8) & 127;
    int b = (idx >> 15) & 7, c = idx >> 18;
    const float* base = channels + (((c * BATCH + b) * H + y) * W) * 4;
    float e0 = base[(2 * j) * 4 + a];
    float e1 = base[(2 * j + 1) * 4 + a];
    int x2 = min(2 * j + 2, W - 1);
    float o1 = base[x2 * 4 + a];
    g_chE[c][b][y][a][j] = pk2(e0, e1);
    g_chO[c][b][y][a][j] = pk2(e1, o1);
}

__global__ void __launch_bounds__(NTHREADS, 2) convsbs_kernel(
    const float* __restrict__ cores,
    float* __restrict__ out)
{
    extern __shared__ float smem[];
    const int tid = threadIdx.x;
    ull* coreU = (ull*)smem;

    // cores relayout: [t][q][l][r][a][c4] -> swizzled per-lane chunks
    for (int idx = tid; idx < 8192; idx += NTHREADS) {
        int c4 = idx & 3, a = (idx >> 2) & 3, r = (idx >> 4) & 7;
        int l = (idx >> 7) & 7, q = (idx >> 10) & 1, t = idx >> 11;
        int bi = t * 2 + q;
        int lr = l * 8 + r;
        int L = lr >> 1, half = lr & 1;
        int ac = a * 4 + c4;
        int chunk = ac >> 1, pos = ac & 1;
        int uidx = bi * 512 + L * 16 + (((chunk + L) & 7) << 1) + pos;
        smem[uidx * 2 + half] = cores[idx];
    }
    __syncthreads();

    const int warp = tid >> 5;
    const int lane = tid & 31;
    ull* Wb = (ull*)(smem + CORES_F) + warp * WARP_ULL;

    const int g2 = lane >> 4;        // q (A-stage) / s (B-stage) / q (final)
    const int i2 = (lane >> 1) & 7;  // i (A) / k (B) / i (final)
    const int h2 = lane & 1;         // k-half (A) / i-half (B)

    const ull z = pk2(0.f, 0.f);
    const int nwork = gridDim.x * WARPS_PER_CTA;

    for (int g = blockIdx.x * WARPS_PER_CTA + warp; g < TOT_GROUPS; g += nwork) {
        int b   = g / (OH * GX);
        int rem = g - b * (OH * GX);
        int y   = rem >> 5;
        int x0  = (rem & 31) << 2;
        const int jbase = x0 >> 1;

        // ========== Stage 1: M for pairs A=(x0+wt, x0+1+wt), B=(x0+2+wt, x0+3+wt) ==========
        #pragma unroll
        for (int t = 0; t < 4; t++) {
            const int py = y + (t >> 1);
            const ull* T0 = (t & 1) ? &g_chO[0][b][py][0][jbase] : &g_chE[0][b][py][0][jbase];
            const ull* T1 = (t & 1) ? &g_chO[1][b][py][0][jbase] : &g_chE[1][b][py][0][jbase];

            // packed channels: pair A at j=jbase, pair B at j=jbase+1 (direct LDG.64)
            ull c0A[4], c1A[4], c0B[4], c1B[4];
            #pragma unroll
            for (int a = 0; a < 4; a++) {
                c0A[a] = T0[a * 64];
                c0B[a] = T0[a * 64 + 1];
                c1A[a] = T1[a * 64];
                c1B[a] = T1[a * 64 + 1];
            }

            ull vA[16], vB[16];
            #pragma unroll
            for (int a = 0; a < 4; a++)
                #pragma unroll
                for (int c = 0; c < 4; c++) {
                    vA[a * 4 + c] = mul2(c0A[a], c1A[c]);
                    vB[a * 4 + c] = mul2(c0B[a], c1B[c]);
                }

            const int row = lane >> 2;        // l of entry lr = 2*lane
            const int col = 2 * (lane & 3);   // r of entry lr = 2*lane
            #pragma unroll
            for (int q = 0; q < 2; q++) {
                const int bi = t * 2 + q;
                const float4* cp4 = (const float4*)(coreU + bi * 512 + lane * 16);
                ull aA0 = z, aA1 = z, aB0 = z, aB1 = z;
                #pragma unroll
                for (int c = 0; c < 8; c++) {
                    float4 f = cp4[(c + lane) & 7];   // ac=2c: (f.x,f.y); ac=2c+1: (f.z,f.w)
                    ull cx2 = pk2(f.x, f.x);
                    ull cy2 = pk2(f.y, f.y);
                    aA0 = fma2(cx2, vA[2 * c], aA0);
                    aA1 = fma2(cy2, vA[2 * c], aA1);
                    aB0 = fma2(cx2, vB[2 * c], aB0);
                    aB1 = fma2(cy2, vB[2 * c], aB1);
                    ull cz2 = pk2(f.z, f.z);
                    ull cw2 = pk2(f.w, f.w);
                    aA0 = fma2(cz2, vA[2 * c + 1], aA0);
                    aA1 = fma2(cw2, vA[2 * c + 1], aA1);
                    aB0 = fma2(cz2, vB[2 * c + 1], aB0);
                    aB1 = fma2(cw2, vB[2 * c + 1], aB1);
                }
                const int midx = bi * MBS + row * 10 + col;
                *(ulonglong2*)(Wb + midx)            = make_ulonglong2(aA0, aA1);
                *(ulonglong2*)(Wb + PAIR_ULL + midx) = make_ulonglong2(aB0, aB1);
            }
        }
        __syncwarp();

        // ========== Stage 2 per pair ==========
        #pragma unroll
        for (int pr = 0; pr < 2; pr++) {
            ull* M = Wb + pr * PAIR_ULL;

            // ---- A-stage: lane (q=g2, i=i2, kh=h2), both p accumulated ----
            ull a2[2][4];
            {
                ull rm0[2][8];
                #pragma unroll
                for (int p = 0; p < 2; p++) {
                    #pragma unroll
                    for (int c = 0; c < 4; c++) {
                        ulonglong2 u = *(const ulonglong2*)(M + p * MBS + i2 * 10 + 2 * c);
                        rm0[p][2 * c] = u.x; rm0[p][2 * c + 1] = u.y;
                    }
                }
                #pragma unroll
                for (int p = 0; p < 2; p++)
                    #pragma unroll
                    for (int kk = 0; kk < 4; kk++) a2[p][kk] = z;
                #pragma unroll
                for (int j = 0; j < 8; j++) {
                    ulonglong2 m1a = *(const ulonglong2*)(M + (2 + g2) * MBS + j * 10 + h2 * 4);
                    ulonglong2 m1b = *(const ulonglong2*)(M + (2 + g2) * MBS + j * 10 + h2 * 4 + 2);
                    #pragma unroll
                    for (int p = 0; p < 2; p++) {
                        a2[p][0] = fma2(rm0[p][j], m1a.x, a2[p][0]);
                        a2[p][1] = fma2(rm0[p][j], m1a.y, a2[p][1]);
                        a2[p][2] = fma2(rm0[p][j], m1b.x, a2[p][2]);
                        a2[p][3] = fma2(rm0[p][j], m1b.y, a2[p][3]);
                    }
                }
            }

            // ---- B-stage: lane (s=g2, k=i2, ih=h2), both r accumulated ----
            ull bt[2][4];
            {
                ull rm2[2][8];
                #pragma unroll
                for (int r = 0; r < 2; r++) {
                    #pragma unroll
                    for (int c = 0; c < 4; c++) {
                        ulonglong2 u = *(const ulonglong2*)(M + (4 + r) * MBS + i2 * 10 + 2 * c);
                        rm2[r][2 * c] = u.x; rm2[r][2 * c + 1] = u.y;
                    }
                }
                #pragma unroll
                for (int r = 0; r < 2; r++)
                    #pragma unroll
                    for (int ii = 0; ii < 4; ii++) bt[r][ii] = z;
                #pragma unroll
                for (int l = 0; l < 8; l++) {
                    ulonglong2 m3a = *(const ulonglong2*)(M + (6 + g2) * MBS + l * 10 + h2 * 4);
                    ulonglong2 m3b = *(const ulonglong2*)(M + (6 + g2) * MBS + l * 10 + h2 * 4 + 2);
                    #pragma unroll
                    for (int r = 0; r < 2; r++) {
                        bt[r][0] = fma2(rm2[r][l], m3a.x, bt[r][0]);
                        bt[r][1] = fma2(rm2[r][l], m3a.y, bt[r][1]);
                        bt[r][2] = fma2(rm2[r][l], m3b.x, bt[r][2]);
                        bt[r][3] = fma2(rm2[r][l], m3b.y, bt[r][3]);
                    }
                }
            }
            __syncwarp();

            // ---- store B: Bsm[rs][k][i] at rs*82 + k*10 + i  (rs = r*2 + s) ----
            #pragma unroll
            for (int r = 0; r < 2; r++) {
                const int base = (r * 2 + g2) * 82 + i2 * 10 + h2 * 4;
                *(ulonglong2*)(M + base)     = make_ulonglong2(bt[r][0], bt[r][1]);
                *(ulonglong2*)(M + base + 2) = make_ulonglong2(bt[r][2], bt[r][3]);
            }
            __syncwarp();

            // ---- final partials at lane (q=g2, i=i2, kh=h2) ----
            ull part[2][4];
            #pragma unroll
            for (int p = 0; p < 2; p++)
                #pragma unroll
                for (int rs = 0; rs < 4; rs++) part[p][rs] = z;
            #pragma unroll
            for (int rs = 0; rs < 4; rs++) {
                #pragma unroll
                for (int kk = 0; kk < 4; kk++) {
                    ull Bv = M[rs * 82 + (h2 * 4 + kk) * 10 + i2];
                    part[0][rs] = fma2(a2[0][kk], Bv, part[0][rs]);
                    part[1][rs] = fma2(a2[1][kk], Bv, part[1][rs]);
                }
            }
            #pragma unroll
            for (int p = 0; p < 2; p++)
                #pragma unroll
                for (int rs = 0; rs < 4; rs++)
                    part[p][rs] = add2(part[p][rs],
                                       __shfl_xor_sync(0xffffffffu, part[p][rs], 1));
            if (h2 == 0) {
                const int pbase = 336 + (g2 * 8 + i2) * 10 + g2 * 8;
                *(ulonglong2*)(M + pbase)     = make_ulonglong2(part[0][0], part[0][1]);
                *(ulonglong2*)(M + pbase + 2) = make_ulonglong2(part[0][2], part[0][3]);
                *(ulonglong2*)(M + pbase + 4) = make_ulonglong2(part[1][0], part[1][1]);
                *(ulonglong2*)(M + pbase + 6) = make_ulonglong2(part[1][2], part[1][3]);
            }
            __syncwarp();

            // ---- output: lanes 0..15, q=lane>>3, o8=lane&7 (p=o8>>2, rs=o8&3) ----
            if (lane < 16) {
                const int q = lane >> 3, o8 = lane & 7;
                ull s = z;
                #pragma unroll
                for (int i = 0; i < 8; i++)
                    s = add2(s, M[336 + (q * 8 + i) * 10 + q * 8 + o8]);
                const int p = o8 >> 2, rs = o8 & 3;
                const int outIdx = p * 8 + q * 4 + rs;
                const int xx = x0 + pr * 2;
                const int pix0 = (b * OH + y) * OW + xx;
                float2 pv = up2(s);
                out[pix0 * 16 + outIdx] = pv.x;
                if (xx + 1 < OW)
                    out[(pix0 + 1) * 16 + outIdx] = pv.y;
            }
            __syncwarp();
        }
    }
}

extern "C" void kernel_launch(void* const* d_in, const int* in_sizes, int n_in,
                              void* d_out, int out_size)
{
    const float* channels = (const float*)d_in[0];
    const float* cores    = (const float*)d_in[1];
    float* out            = (float*)d_out;

    static bool attr_set = false;
    if (!attr_set) {
        cudaFuncSetAttribute(convsbs_kernel,
                             cudaFuncAttributeMaxDynamicSharedMemorySize,
                             SMEM_F * sizeof(float));
        attr_set = true;
    }
    transpose_kernel<<<512, 1024>>>(channels);
    convsbs_kernel<<<NCTAS, NTHREADS, SMEM_F * sizeof(float)>>>(cores, out);
}